// round 5
// baseline (speedup 1.0000x reference)
#include <cuda_runtime.h>
#include <cstdint>
#include <math.h>

#define BATCH 8
#define NPTS 4096

// ---------------- scratch (static device globals; no allocation) ----------------
__device__ float g_feat[BATCH*8*NPTS];
__device__ float g_h   [BATCH*32*NPTS*16];      // reused by all stages
__device__ float g_kf1 [BATCH*32*NPTS];
__device__ float g_qc1 [BATCH*3*1024];
__device__ float g_qf1 [BATCH*32*1024];
__device__ float g_qf2 [BATCH*64*1024];
__device__ float g_kf3 [BATCH*64*1024];
__device__ float g_qf4 [BATCH*64*256];
__device__ int   g_idx1[BATCH*NPTS*16];
__device__ int   g_idx2[BATCH*1024*16];
__device__ int   g_idx3[BATCH*1024*16];
__device__ int   g_idx4[BATCH*256*16];
__device__ int   g_fps1[BATCH*1024];
__device__ int   g_fps2[BATCH*256];
__device__ float g_stats[64];
__device__ float g_musig[64];

// ---------------- f32x2 packed helpers (rn per-lane, bitwise == scalar rn) ----------------
__device__ __forceinline__ unsigned long long pk2(float a, float b) {
    unsigned long long r; asm("mov.b64 %0,{%1,%2};" : "=l"(r) : "f"(a), "f"(b)); return r;
}
__device__ __forceinline__ void upk2(unsigned long long v, float& a, float& b) {
    asm("mov.b64 {%0,%1},%2;" : "=f"(a), "=f"(b) : "l"(v));
}
__device__ __forceinline__ unsigned long long addx2(unsigned long long a, unsigned long long b) {
    unsigned long long r; asm("add.rn.f32x2 %0,%1,%2;" : "=l"(r) : "l"(a), "l"(b)); return r;
}
__device__ __forceinline__ unsigned long long mulx2(unsigned long long a, unsigned long long b) {
    unsigned long long r; asm("mul.rn.f32x2 %0,%1,%2;" : "=l"(r) : "l"(a), "l"(b)); return r;
}

// ---------------- pointwise transform: feat = Wt @ pc + bt ----------------
__global__ void transform_kernel(const float* __restrict__ pc, const float* __restrict__ Wt,
                                 const float* __restrict__ bt, float* __restrict__ feat)
{
    int i = blockIdx.x*256 + threadIdx.x;
    if (i >= BATCH*8*NPTS) return;
    int n = i & (NPTS-1);
    int o = (i >> 12) & 7;
    int b = i >> 15;
    const float* p = pc + (size_t)b*3*NPTS;
    float v = Wt[o*3+0]*p[n] + Wt[o*3+1]*p[NPTS+n] + Wt[o*3+2]*p[2*NPTS+n] + bt[o];
    feat[i] = v;
}

// ---------------- knn insert (top-16 smallest, JAX top_k tie-break) ----------------
__device__ __forceinline__ void knn_insert(unsigned long long (*skey)[256], int tid,
                                           float d, unsigned idx, float& worstf, int& wslot)
{
    unsigned ub = __float_as_uint(d);
    ub ^= ((int)ub < 0) ? 0xFFFFFFFFu : 0x80000000u;   // order-preserving map
    unsigned long long key = ((unsigned long long)ub << 32) | idx;
    skey[wslot][tid] = key;
    unsigned long long w = 0ULL; int ws = 0;
    #pragma unroll
    for (int s = 0; s < 16; s++) {
        unsigned long long v = skey[s][tid];
        if (v > w) { w = v; ws = s; }
    }
    wslot = ws;
    if (w == 0xFFFFFFFFFFFFFFFFULL) {
        worstf = __int_as_float(0x7f800000);           // slots not yet full -> +inf
    } else {
        unsigned m = (unsigned)(w >> 32);
        unsigned orig = (m & 0x80000000u) ? (m ^ 0x80000000u) : ~m;
        worstf = __uint_as_float(orig);
    }
}

// ---------------- knn device function (k=16): paired f32x2 distance loop ----------------
// smem: [ulonglong2 kxy[512] | ulonglong2 kzw[512]] = 16KB, then skey[16][256] = 32KB.
// d2 = (q2+k2) + (-2)*dt: fsub(a,b)==fadd(a,-b) and -(2*dt)==(-2)*dt bitwise in rn,
// so this matches the reference op sequence exactly per lane.
__device__ void knn_dev(const float* __restrict__ qb, const float* __restrict__ kb,
                        int Q, int NK, int* __restrict__ out, int qbase, char* smemraw)
{
    ulonglong2* kxy = (ulonglong2*)smemraw;
    ulonglong2* kzw = kxy + 512;
    unsigned long long (*skey)[256] = (unsigned long long (*)[256])(smemraw + 16384);
    const int tid = threadIdx.x;
    const int q = qbase + tid;

    float qx = qb[q], qy = qb[Q+q], qz = qb[2*Q+q];
    float q2 = __fadd_rn(__fadd_rn(__fmul_rn(qx,qx), __fmul_rn(qy,qy)), __fmul_rn(qz,qz));
    unsigned long long qx2 = pk2(qx,qx), qy2 = pk2(qy,qy), qz2 = pk2(qz,qz);
    unsigned long long q22 = pk2(q2,q2), n2 = pk2(-2.0f,-2.0f);

    #pragma unroll
    for (int s = 0; s < 16; s++) skey[s][tid] = 0xFFFFFFFFFFFFFFFFULL;
    float worstf = __int_as_float(0x7f800000);   // +inf
    int wslot = 0;

    for (int t0 = 0; t0 < NK; t0 += 1024) {
        int halfn = min(1024, NK - t0) >> 1;
        __syncthreads();
        for (int i = tid; i < halfn; i += 256) {
            float2 x01 = ((const float2*)(kb + t0))[i];
            float2 y01 = ((const float2*)(kb + NK + t0))[i];
            float2 z01 = ((const float2*)(kb + 2*NK + t0))[i];
            float k20 = __fadd_rn(__fadd_rn(__fmul_rn(x01.x,x01.x), __fmul_rn(y01.x,y01.x)), __fmul_rn(z01.x,z01.x));
            float k21 = __fadd_rn(__fadd_rn(__fmul_rn(x01.y,x01.y), __fmul_rn(y01.y,y01.y)), __fmul_rn(z01.y,z01.y));
            ulonglong2 a; a.x = pk2(x01.x, x01.y); a.y = pk2(y01.x, y01.y);
            ulonglong2 c; c.x = pk2(z01.x, z01.y); c.y = pk2(k20, k21);
            kxy[i] = a; kzw[i] = c;
        }
        __syncthreads();
        #pragma unroll 4
        for (int j = 0; j < halfn; j++) {
            ulonglong2 a = kxy[j];
            ulonglong2 c = kzw[j];
            unsigned long long dt2 = addx2(addx2(mulx2(qx2,a.x), mulx2(qy2,a.y)), mulx2(qz2,c.x));
            unsigned long long d2p = addx2(addx2(q22, c.y), mulx2(n2, dt2));
            float d0, d1; upk2(d2p, d0, d1);
            // strict float test is exact: equal-d2 at larger index always loses the key compare
            if (d0 < worstf) knn_insert(skey, tid, d0, (unsigned)(t0 + 2*j),     worstf, wslot);
            if (d1 < worstf) knn_insert(skey, tid, d1, (unsigned)(t0 + 2*j + 1), worstf, wslot);
        }
    }
    #pragma unroll
    for (int s = 0; s < 16; s++)
        out[(size_t)q*16 + s] = (int)(skey[s][tid] & 0xFFFFFFFFu);
}

// ---------------- FPS device function (256 threads, 1 barrier/iter, no atomics) ----------------
// Per-iteration: exact rn distance update (packed f32x2), FMNMX local-max tree,
// REDUX warp max; only warps holding the max run a first-index scan. Per-warp keys
// (rmax<<32 | ~idx) in a double-buffered skeys[2][8]; one barrier; all threads scan.
template<int NP, int M>
__device__ void fps_dev(const float* __restrict__ cb, int* __restrict__ outi, char* smemraw)
{
    constexpr int PPT = NP / 256;
    constexpr int PAIRS = PPT / 2;
    static_assert(PPT * 256 == NP && PAIRS * 2 == PPT, "layout");
    const int tid  = threadIdx.x;
    const int warp = tid >> 5;
    unsigned long long (*skeys)[8] = (unsigned long long (*)[8])smemraw;   // [2][8]

    unsigned long long xp[PAIRS], yp[PAIRS], zp[PAIRS];
    float d_[PPT];
    #pragma unroll
    for (int pr = 0; pr < PAIRS; pr++) {
        int i0 = (2*pr)*256 + tid, i1 = (2*pr+1)*256 + tid;
        xp[pr] = pk2(cb[i0],        cb[i1]);
        yp[pr] = pk2(cb[NP+i0],     cb[NP+i1]);
        zp[pr] = pk2(cb[2*NP+i0],   cb[2*NP+i1]);
        d_[2*pr] = 1e10f; d_[2*pr+1] = 1e10f;
    }
    if (tid == 0) outi[0] = 0;

    int last = 0;
    for (int t = 1; t < M; t++) {
        float px = __ldg(cb + last), py = __ldg(cb + NP + last), pz = __ldg(cb + 2*NP + last);
        unsigned long long pxn = pk2(-px, -px), pyn = pk2(-py, -py), pzn = pk2(-pz, -pz);
        float lm = -1.0f;
        #pragma unroll
        for (int pr = 0; pr < PAIRS; pr++) {
            // exact reference sequence per lane: sub, 3x mul, 2x add (NO fma)
            unsigned long long dx = addx2(xp[pr], pxn);
            unsigned long long dy = addx2(yp[pr], pyn);
            unsigned long long dz = addx2(zp[pr], pzn);
            unsigned long long s2 = addx2(addx2(mulx2(dx,dx), mulx2(dy,dy)), mulx2(dz,dz));
            float m0, m1; upk2(s2, m0, m1);
            float d0 = fminf(d_[2*pr],   m0); d_[2*pr]   = d0;
            float d1 = fminf(d_[2*pr+1], m1); d_[2*pr+1] = d1;
            lm = fmaxf(lm, fmaxf(d0, d1));
        }
        // warp argmax with first-index tie-break (matches jnp.argmax):
        unsigned db   = __float_as_uint(lm);               // d >= 0 so bits ordered
        unsigned rmax = __reduce_max_sync(0xFFFFFFFFu, db);
        unsigned inv  = 0u;
        if (db == rmax) {                                   // rare path: winner warp(s) only
            int idx = 0x7FFFFFF0;
            #pragma unroll
            for (int p = PPT-1; p >= 0; p--)
                if (__float_as_uint(d_[p]) == db) idx = p*256 + tid;
            inv = 0xFFFFFFFFu - (unsigned)idx;
        }
        unsigned invmax = __reduce_max_sync(0xFFFFFFFFu, inv);
        if ((tid & 31) == 0)
            skeys[t & 1][warp] = ((unsigned long long)rmax << 32) | invmax;
        __syncthreads();
        const unsigned long long* kk = skeys[t & 1];
        unsigned long long k0 = kk[0] > kk[1] ? kk[0] : kk[1];
        unsigned long long k1 = kk[2] > kk[3] ? kk[2] : kk[3];
        unsigned long long k2 = kk[4] > kk[5] ? kk[4] : kk[5];
        unsigned long long k3 = kk[6] > kk[7] ? kk[6] : kk[7];
        k0 = k0 > k1 ? k0 : k1;
        k2 = k2 > k3 ? k2 : k3;
        k0 = k0 > k2 ? k0 : k2;
        last = (int)(0xFFFFFFFFu - (unsigned)(k0 & 0xFFFFFFFFu));
        if (tid == 0) outi[t] = last;
    }
}

// ---------------- mega kernel 1: knn1 (128 blocks) || fps1 (8 blocks) ----------------
__global__ void __launch_bounds__(256) mega1_kernel(const float* __restrict__ pc,
                                                    int* __restrict__ idx1,
                                                    int* __restrict__ fps1)
{
    extern __shared__ char smem[];
    int blk = blockIdx.x;
    if (blk < 128) {
        int b = blk >> 4, chunk = blk & 15;
        knn_dev(pc + (size_t)b*3*NPTS, pc + (size_t)b*3*NPTS, NPTS, NPTS,
                idx1 + (size_t)b*NPTS*16, chunk*256, smem);
    } else {
        int b = blk - 128;
        fps_dev<4096,1024>(pc + (size_t)b*3*NPTS, fps1 + (size_t)b*1024, smem);
    }
}

// ---------------- mega kernel 2: knn2 (32) || knn3 (32) || fps2 (8) ----------------
__global__ void __launch_bounds__(256) mega2_kernel(const float* __restrict__ pc,
                                                    const float* __restrict__ qc1,
                                                    int* __restrict__ idx2,
                                                    int* __restrict__ idx3,
                                                    int* __restrict__ fps2)
{
    extern __shared__ char smem[];
    int blk = blockIdx.x;
    if (blk < 32) {
        int b = blk >> 2, chunk = blk & 3;
        knn_dev(qc1 + (size_t)b*3*1024, pc + (size_t)b*3*NPTS, 1024, NPTS,
                idx2 + (size_t)b*1024*16, chunk*256, smem);
    } else if (blk < 64) {
        int bb = blk - 32;
        int b = bb >> 2, chunk = bb & 3;
        knn_dev(qc1 + (size_t)b*3*1024, qc1 + (size_t)b*3*1024, 1024, 1024,
                idx3 + (size_t)b*1024*16, chunk*256, smem);
    } else {
        int b = blk - 64;
        fps_dev<1024,256>(qc1 + (size_t)b*3*1024, fps2 + (size_t)b*256, smem);
    }
}

// ---------------- knn4 (needs gathered out coords) ----------------
__global__ void __launch_bounds__(256) knn4_kernel(const float* __restrict__ qc,
                                                   int* __restrict__ idx4)
{
    extern __shared__ char smem[];
    int b = blockIdx.x;
    knn_dev(qc + (size_t)b*3*256, qc + (size_t)b*3*256, 256, 256,
            idx4 + (size_t)b*256*16, 0, smem);
}

// ---------------- gather: dst[b,c,m] = src[b,c,idx[b,m]] ----------------
__global__ void gather_kernel(const float* __restrict__ src, const int* __restrict__ idx,
                              float* __restrict__ dst, int C, int Nsrc, int M)
{
    int i = blockIdx.x*256 + threadIdx.x;
    if (i >= BATCH*C*M) return;
    int m = i % M; int c = (i/M) % C; int b = i/(M*C);
    dst[i] = src[((size_t)b*C + c)*Nsrc + idx[(size_t)b*M + m]];
}

// ---------------- edge conv pass 1: h = W @ [neigh-qe; qe], + group stats ----------------
template<int C, int O>
__global__ void edge_h_kernel(const float* __restrict__ kf, const float* __restrict__ qf,
                              const int* __restrict__ idx, const float* __restrict__ W,
                              float* __restrict__ h, float* __restrict__ stats,
                              int Q, int NK)
{
    extern __shared__ float smemf[];
    float* sW   = smemf;                // O*2C
    float* sqf  = sW  + O*2*C;          // [c*16+ql]
    float* sqb  = sqf + C*16;           // [ql*O+o]
    float* sred = sqb + 16*O;           // 8 warps * 8

    const int tid   = threadIdx.x;
    const int b     = blockIdx.y;
    const int qbase = blockIdx.x*16;

    for (int i = tid; i < O*2*C; i += 256) sW[i] = W[i];
    for (int i = tid; i < C*16;  i += 256)
        sqf[i] = qf[((size_t)b*C + (i >> 4))*Q + qbase + (i & 15)];
    __syncthreads();

    for (int e = tid; e < 16*O; e += 256) {
        int ql = e / O, o = e - ql*O;
        float acc = 0.f;
        #pragma unroll
        for (int c = 0; c < C; c++) acc = fmaf(sW[o*2*C + C + c], sqf[c*16 + ql], acc);
        sqb[e] = acc;
    }
    __syncthreads();

    const int ql = tid >> 4, k = tid & 15;
    const int q = qbase + ql;
    const int j = idx[((size_t)b*Q + q)*16 + k];

    float e_[C];
    #pragma unroll
    for (int c = 0; c < C; c++)
        e_[c] = kf[((size_t)b*C + c)*NK + j] - sqf[c*16 + ql];

    float* hp = h + ((size_t)b*O*Q + q)*16 + k;
    const float* sqbp = sqb + ql*O;
    const int lane = tid & 31, warp = tid >> 5;

    #pragma unroll
    for (int g = 0; g < 4; g++) {
        float s = 0.f, ss = 0.f;
        for (int o = g*(O/4); o < (g+1)*(O/4); o++) {
            float acc = sqbp[o];
            const float* wr = sW + o*2*C;
            #pragma unroll
            for (int c = 0; c < C; c++) acc = fmaf(wr[c], e_[c], acc);
            hp[(size_t)o*Q*16] = acc;
            s += acc; ss = fmaf(acc, acc, ss);
        }
        #pragma unroll
        for (int off = 16; off; off >>= 1) {
            s  += __shfl_xor_sync(0xFFFFFFFFu, s,  off);
            ss += __shfl_xor_sync(0xFFFFFFFFu, ss, off);
        }
        if (lane == 0) { sred[warp*8 + g*2] = s; sred[warp*8 + g*2 + 1] = ss; }
    }
    __syncthreads();
    if (tid < 8) {
        float t = 0.f;
        #pragma unroll
        for (int w = 0; w < 8; w++) t += sred[w*8 + tid];
        atomicAdd(&stats[b*8 + tid], t);
    }
}

// ---------------- stats ----------------
__global__ void zero_stats_kernel(float* __restrict__ stats)
{
    int i = threadIdx.x;
    if (i < 64) stats[i] = 0.f;
}
__global__ void stats_fin_kernel(const float* __restrict__ stats, float* __restrict__ musig,
                                 float inv_cnt)
{
    int i = threadIdx.x;
    if (i < 32) {
        float s = stats[i*2], ss = stats[i*2+1];
        float mu  = s * inv_cnt;
        float var = ss * inv_cnt - mu*mu;
        musig[i*2]   = mu;
        musig[i*2+1] = 1.0f / sqrtf(var + 1e-5f);
    }
}

// ---------------- edge conv pass 2: GN + leaky + max over k ----------------
__global__ void edge_out_kernel(const float* __restrict__ h, const float* __restrict__ musig,
                                const float* __restrict__ gamma, const float* __restrict__ beta,
                                float* __restrict__ out, int O, int O4, int Q)
{
    int i = blockIdx.x*256 + threadIdx.x;
    if (i >= BATCH*O*Q) return;
    int o = (i / Q) % O;
    int b = i / (Q*O);
    int g = o / O4;
    float mu   = musig[(b*4+g)*2];
    float rstd = musig[(b*4+g)*2+1];
    float ga = gamma[o], be = beta[o];
    const float4* hp = (const float4*)(h + (size_t)i*16);
    float m = -INFINITY;
    #pragma unroll
    for (int r = 0; r < 4; r++) {
        float4 v = hp[r];
        float vv[4] = {v.x, v.y, v.z, v.w};
        #pragma unroll
        for (int c = 0; c < 4; c++) {
            float xn = (vv[c] - mu) * rstd;
            float y  = xn * ga + be;
            y = (y >= 0.f) ? y : 0.2f * y;
            m = fmaxf(m, y);
        }
    }
    out[i] = m;
}

// ---------------- host orchestration ----------------
static inline int eh_smem(int C, int O) { return (O*2*C + 16*C + 16*O + 64) * 4; }
#define KNN_SMEM 49152

extern "C" void kernel_launch(void* const* d_in, const int* in_sizes, int n_in,
                              void* d_out, int out_size)
{
    const float* pc = (const float*)d_in[0];
    const float* Wt = (const float*)d_in[1];
    const float* bt = (const float*)d_in[2];
    const float* W1 = (const float*)d_in[3];
    const float* g1 = (const float*)d_in[4];
    const float* b1 = (const float*)d_in[5];
    const float* W2 = (const float*)d_in[6];
    const float* g2 = (const float*)d_in[7];
    const float* b2 = (const float*)d_in[8];
    const float* W3 = (const float*)d_in[9];
    const float* g3 = (const float*)d_in[10];
    const float* b3 = (const float*)d_in[11];
    const float* W4 = (const float*)d_in[12];
    const float* g4 = (const float*)d_in[13];
    const float* b4 = (const float*)d_in[14];
    float* out = (float*)d_out;

    float *feat, *h, *kf1, *qc1, *qf1, *qf2, *kf3, *qf4, *stats, *musig;
    int *idx1, *idx2, *idx3, *idx4, *fps1, *fps2;
    cudaGetSymbolAddress((void**)&feat,  g_feat);
    cudaGetSymbolAddress((void**)&h,     g_h);
    cudaGetSymbolAddress((void**)&kf1,   g_kf1);
    cudaGetSymbolAddress((void**)&qc1,   g_qc1);
    cudaGetSymbolAddress((void**)&qf1,   g_qf1);
    cudaGetSymbolAddress((void**)&qf2,   g_qf2);
    cudaGetSymbolAddress((void**)&kf3,   g_kf3);
    cudaGetSymbolAddress((void**)&qf4,   g_qf4);
    cudaGetSymbolAddress((void**)&stats, g_stats);
    cudaGetSymbolAddress((void**)&musig, g_musig);
    cudaGetSymbolAddress((void**)&idx1,  g_idx1);
    cudaGetSymbolAddress((void**)&idx2,  g_idx2);
    cudaGetSymbolAddress((void**)&idx3,  g_idx3);
    cudaGetSymbolAddress((void**)&idx4,  g_idx4);
    cudaGetSymbolAddress((void**)&fps1,  g_fps1);
    cudaGetSymbolAddress((void**)&fps2,  g_fps2);

    cudaFuncSetAttribute(edge_h_kernel<64,128>,
                         cudaFuncAttributeMaxDynamicSharedMemorySize, eh_smem(64,128));

    // launches 1-3: transform + two idempotent stat zeroes (pads mega1 to launch #4,
    // which is the launch ncu's -s/-c window captures -> attribution next round)
    transform_kernel<<<(BATCH*8*NPTS+255)/256, 256>>>(pc, Wt, bt, feat);
    zero_stats_kernel<<<1,64>>>(stats);
    zero_stats_kernel<<<1,64>>>(stats);

    // launch #4: knn1 (128 blocks) || fps1 (8 blocks), one wave of 136
    mega1_kernel<<<136, 256, KNN_SMEM>>>(pc, idx1, fps1);

    // edge_conv 1: C=8 -> O=32
    zero_stats_kernel<<<1,64>>>(stats);
    edge_h_kernel<8,32><<<dim3(NPTS/16, BATCH), 256, eh_smem(8,32)>>>(feat, feat, idx1, W1, h, stats, NPTS, NPTS);
    stats_fin_kernel<<<1,32>>>(stats, musig, 1.0f/524288.0f);
    edge_out_kernel<<<(BATCH*32*NPTS+255)/256, 256>>>(h, musig, g1, b1, kf1, 32, 8, NPTS);

    // gather after fps1
    gather_kernel<<<(BATCH*3*1024+255)/256, 256>>>(pc,  fps1, qc1, 3,  NPTS, 1024);
    gather_kernel<<<(BATCH*32*1024+255)/256,256>>>(kf1, fps1, qf1, 32, NPTS, 1024);

    // knn2 + knn3 + fps2 concurrently (72 blocks)
    mega2_kernel<<<72, 256, KNN_SMEM>>>(pc, qc1, idx2, idx3, fps2);

    // edge_conv 2: C=32 -> O=64
    zero_stats_kernel<<<1,64>>>(stats);
    edge_h_kernel<32,64><<<dim3(1024/16, BATCH), 256, eh_smem(32,64)>>>(kf1, qf1, idx2, W2, h, stats, 1024, NPTS);
    stats_fin_kernel<<<1,32>>>(stats, musig, 1.0f/262144.0f);
    edge_out_kernel<<<(BATCH*64*1024+255)/256, 256>>>(h, musig, g2, b2, qf2, 64, 16, 1024);

    // edge_conv 3: C=64 -> O=64
    zero_stats_kernel<<<1,64>>>(stats);
    edge_h_kernel<64,64><<<dim3(1024/16, BATCH), 256, eh_smem(64,64)>>>(qf2, qf2, idx3, W3, h, stats, 1024, 1024);
    stats_fin_kernel<<<1,32>>>(stats, musig, 1.0f/262144.0f);
    edge_out_kernel<<<(BATCH*64*1024+255)/256, 256>>>(h, musig, g3, b3, kf3, 64, 16, 1024);

    // gather after fps2 (coords straight into d_out)
    gather_kernel<<<(BATCH*3*256+255)/256, 256>>>(qc1, fps2, out, 3, 1024, 256);
    gather_kernel<<<(BATCH*64*256+255)/256,256>>>(kf3, fps2, qf4, 64, 1024, 256);

    // edge_conv 4: knn(256x256), C=64 -> O=128
    knn4_kernel<<<8, 256, KNN_SMEM>>>(out, idx4);
    zero_stats_kernel<<<1,64>>>(stats);
    edge_h_kernel<64,128><<<dim3(256/16, BATCH), 256, eh_smem(64,128)>>>(qf4, qf4, idx4, W4, h, stats, 256, 256);
    stats_fin_kernel<<<1,32>>>(stats, musig, 1.0f/131072.0f);
    edge_out_kernel<<<(BATCH*128*256+255)/256, 256>>>(h, musig, g4, b4, out + BATCH*3*256, 128, 32, 256);
}

// round 7
// speedup vs baseline: 1.9519x; 1.9519x over previous
#include <cuda_runtime.h>
#include <cstdint>
#include <math.h>

#define BATCH 8
#define NPTS 4096

// ---------------- scratch (static device globals; no allocation) ----------------
__device__ float g_feat[BATCH*8*NPTS];
__device__ float g_h   [BATCH*32*NPTS*16];      // reused by all stages
__device__ float g_kf1 [BATCH*32*NPTS];
__device__ float g_qc1 [BATCH*3*1024];
__device__ float g_qf1 [BATCH*32*1024];
__device__ float g_qf2 [BATCH*64*1024];
__device__ float g_kf3 [BATCH*64*1024];
__device__ float g_qf4 [BATCH*64*256];
__device__ int   g_idx1[BATCH*NPTS*16];
__device__ int   g_idx2[BATCH*1024*16];
__device__ int   g_idx3[BATCH*1024*16];
__device__ int   g_idx4[BATCH*256*16];
__device__ int   g_fps1[BATCH*1024];
__device__ int   g_fps2[BATCH*256];
__device__ float g_stats[64];
__device__ float g_musig[64];

// ---------------- f32x2 packed helpers (used ONLY in fps, validated lineage) ---
__device__ __forceinline__ unsigned long long pk2(float a, float b) {
    unsigned long long r; asm("mov.b64 %0,{%1,%2};" : "=l"(r) : "f"(a), "f"(b)); return r;
}
__device__ __forceinline__ void upk2(unsigned long long v, float& a, float& b) {
    asm("mov.b64 {%0,%1},%2;" : "=f"(a), "=f"(b) : "l"(v));
}
__device__ __forceinline__ unsigned long long addx2(unsigned long long a, unsigned long long b) {
    unsigned long long r; asm("add.rn.f32x2 %0,%1,%2;" : "=l"(r) : "l"(a), "l"(b)); return r;
}
__device__ __forceinline__ unsigned long long mulx2(unsigned long long a, unsigned long long b) {
    unsigned long long r; asm("mul.rn.f32x2 %0,%1,%2;" : "=l"(r) : "l"(a), "l"(b)); return r;
}

// ---------------- pointwise transform: feat = Wt @ pc + bt ----------------
__global__ void transform_kernel(const float* __restrict__ pc, const float* __restrict__ Wt,
                                 const float* __restrict__ bt, float* __restrict__ feat)
{
    int i = blockIdx.x*256 + threadIdx.x;
    if (i >= BATCH*8*NPTS) return;
    int n = i & (NPTS-1);
    int o = (i >> 12) & 7;
    int b = i >> 15;
    const float* p = pc + (size_t)b*3*NPTS;
    float v = Wt[o*3+0]*p[n] + Wt[o*3+1]*p[NPTS+n] + Wt[o*3+2]*p[2*NPTS+n] + bt[o];
    feat[i] = v;
}

// ---------------- knn insert: tournament-tree argmax over 16 shared slots ------
// Replaces the serial 16-step u64 max chain (depth 16 x ~8cyc) with a depth-4
// tree: same op count, 4x less exposed latency at 2 warps/SMSP.
__device__ __forceinline__ void knn_insert16(unsigned long long (*skey)[256], int tid,
                                             unsigned long long key, float& worstf, int& wslot)
{
    skey[wslot][tid] = key;
    unsigned long long v[8]; int ix[8];
    #pragma unroll
    for (int s = 0; s < 8; s++) {
        unsigned long long a = skey[2*s][tid], b = skey[2*s+1][tid];
        bool p = b > a;
        v[s] = p ? b : a; ix[s] = p ? 2*s+1 : 2*s;
    }
    #pragma unroll
    for (int s = 0; s < 4; s++) {
        bool p = v[2*s+1] > v[2*s];
        v[s] = p ? v[2*s+1] : v[2*s]; ix[s] = p ? ix[2*s+1] : ix[2*s];
    }
    bool pa = v[1] > v[0]; unsigned long long va = pa ? v[1] : v[0]; int ia = pa ? ix[1] : ix[0];
    bool pb = v[3] > v[2]; unsigned long long vb = pb ? v[3] : v[2]; int ib = pb ? ix[3] : ix[2];
    bool pf = vb > va;     unsigned long long w  = pf ? vb : va;     wslot = pf ? ib : ia;
    if (w == 0xFFFFFFFFFFFFFFFFULL) {
        worstf = __int_as_float(0x7f800000);           // slots not yet full -> +inf
    } else {
        unsigned m = (unsigned)(w >> 32);
        unsigned orig = (m & 0x80000000u) ? (m ^ 0x80000000u) : ~m;
        worstf = __uint_as_float(orig);
    }
}

// ---------------- knn device function (k=16 smallest d2, JAX top_k tie-break) --
// Scalar rn distance path (proven bit-exact vs reference). smem: float4 tile
// [1024] = 16KB, then skey[16][256] = 32KB. Total 48KB.
__device__ void knn_dev(const float* __restrict__ qb, const float* __restrict__ kb,
                        int Q, int NK, int* __restrict__ out, int qbase, char* smemraw)
{
    float4* tile = (float4*)smemraw;
    unsigned long long (*skey)[256] = (unsigned long long (*)[256])(smemraw + 16384);
    const int tid = threadIdx.x;
    const int q = qbase + tid;

    float qx = qb[q], qy = qb[Q+q], qz = qb[2*Q+q];
    float q2 = __fadd_rn(__fadd_rn(__fmul_rn(qx,qx), __fmul_rn(qy,qy)), __fmul_rn(qz,qz));

    #pragma unroll
    for (int s = 0; s < 16; s++) skey[s][tid] = 0xFFFFFFFFFFFFFFFFULL;
    float worstf = __int_as_float(0x7f800000);   // +inf
    int wslot = 0;

    for (int t0 = 0; t0 < NK; t0 += 1024) {
        int tn = min(1024, NK - t0);
        __syncthreads();
        for (int i = tid; i < tn; i += 256) {
            float kx = kb[t0+i], ky = kb[NK+t0+i], kz = kb[2*NK+t0+i];
            float k2 = __fadd_rn(__fadd_rn(__fmul_rn(kx,kx), __fmul_rn(ky,ky)), __fmul_rn(kz,kz));
            tile[i] = make_float4(kx, ky, kz, k2);
        }
        __syncthreads();
        #pragma unroll 2
        for (int j = 0; j < tn; j++) {
            float4 kv = tile[j];
            float dt = __fadd_rn(__fadd_rn(__fmul_rn(qx,kv.x), __fmul_rn(qy,kv.y)), __fmul_rn(qz,kv.z));
            float d2 = __fsub_rn(__fadd_rn(q2, kv.w), __fmul_rn(2.0f, dt));
            // strict float test is exact: equal-d2 at larger scan index loses anyway
            if (d2 < worstf) {
                unsigned ub = __float_as_uint(d2);
                ub ^= ((int)ub < 0) ? 0xFFFFFFFFu : 0x80000000u;   // order-preserving map
                unsigned long long key = ((unsigned long long)ub << 32) | (unsigned)(t0 + j);
                knn_insert16(skey, tid, key, worstf, wslot);
            }
        }
    }
    #pragma unroll
    for (int s = 0; s < 16; s++)
        out[(size_t)q*16 + s] = (int)(skey[s][tid] & 0xFFFFFFFFu);
}

// ---------------- FPS device function (r4-proven form: 1 barrier/iter) --------
// Per-warp winners via plain STS to a double-buffered skeys[2][8]; one barrier;
// every thread scans the 8 keys. Key = (dist_bits<<32)|(~idx): max-compare ==
// argmax with first-index tie-break (matches jnp.argmax).
template<int NP, int M>
__device__ void fps_dev(const float* __restrict__ cb, int* __restrict__ outi, char* smemraw)
{
    constexpr int PPT = NP / 256;
    constexpr int PAIRS = PPT / 2;
    static_assert(PPT * 256 == NP && PAIRS * 2 == PPT, "layout");
    const int tid  = threadIdx.x;
    const int warp = tid >> 5;
    unsigned long long (*skeys)[8] = (unsigned long long (*)[8])smemraw;   // [2][8]

    unsigned long long xp[PAIRS], yp[PAIRS], zp[PAIRS];
    float d_[PPT];
    #pragma unroll
    for (int pr = 0; pr < PAIRS; pr++) {
        int i0 = (2*pr)*256 + tid, i1 = (2*pr+1)*256 + tid;
        xp[pr] = pk2(cb[i0],        cb[i1]);
        yp[pr] = pk2(cb[NP+i0],     cb[NP+i1]);
        zp[pr] = pk2(cb[2*NP+i0],   cb[2*NP+i1]);
        d_[2*pr] = 1e10f; d_[2*pr+1] = 1e10f;
    }
    if (tid == 0) outi[0] = 0;

    int last = 0;
    for (int t = 1; t < M; t++) {
        float px = __ldg(cb + last), py = __ldg(cb + NP + last), pz = __ldg(cb + 2*NP + last);
        unsigned long long pxn = pk2(-px, -px), pyn = pk2(-py, -py), pzn = pk2(-pz, -pz);
        float bestd = -1.0f; int besti = 0;
        #pragma unroll
        for (int pr = 0; pr < PAIRS; pr++) {
            // exact reference sequence per lane: sub, 3x mul, 2x add (NO fma)
            unsigned long long dx = addx2(xp[pr], pxn);
            unsigned long long dy = addx2(yp[pr], pyn);
            unsigned long long dz = addx2(zp[pr], pzn);
            unsigned long long s2 = addx2(addx2(mulx2(dx,dx), mulx2(dy,dy)), mulx2(dz,dz));
            float m0, m1; upk2(s2, m0, m1);
            float d0 = fminf(d_[2*pr],   m0); d_[2*pr]   = d0;
            float d1 = fminf(d_[2*pr+1], m1); d_[2*pr+1] = d1;
            if (d0 > bestd) { bestd = d0; besti = (2*pr)*256 + tid; }
            if (d1 > bestd) { bestd = d1; besti = (2*pr+1)*256 + tid; }
        }
        unsigned db     = __float_as_uint(bestd);          // d >= 0 so bits ordered
        unsigned rmax   = __reduce_max_sync(0xFFFFFFFFu, db);
        unsigned inv    = (db == rmax) ? (0xFFFFFFFFu - (unsigned)besti) : 0u;
        unsigned invmax = __reduce_max_sync(0xFFFFFFFFu, inv);
        if ((tid & 31) == 0)
            skeys[t & 1][warp] = ((unsigned long long)rmax << 32) | invmax;
        __syncthreads();
        const unsigned long long* kk = skeys[t & 1];
        unsigned long long k0 = kk[0] > kk[1] ? kk[0] : kk[1];
        unsigned long long k1 = kk[2] > kk[3] ? kk[2] : kk[3];
        unsigned long long k2 = kk[4] > kk[5] ? kk[4] : kk[5];
        unsigned long long k3 = kk[6] > kk[7] ? kk[6] : kk[7];
        k0 = k0 > k1 ? k0 : k1;
        k2 = k2 > k3 ? k2 : k3;
        k0 = k0 > k2 ? k0 : k2;
        last = (int)(0xFFFFFFFFu - (unsigned)(k0 & 0xFFFFFFFFu));
        if (tid == 0) outi[t] = last;
    }
}

// ---------------- edge conv pass 1 device fn: h = W @ [neigh-qe; qe] + stats ---
template<int C, int O>
__device__ void edge_h_dev(const float* __restrict__ kf, const float* __restrict__ qf,
                           const int* __restrict__ idx, const float* __restrict__ W,
                           float* __restrict__ h, float* __restrict__ stats,
                           int Q, int NK, int b, int qbase, char* smemraw)
{
    float* sW   = (float*)smemraw;      // O*2C
    float* sqf  = sW  + O*2*C;          // [c*16+ql]
    float* sqb  = sqf + C*16;           // [ql*O+o]
    float* sred = sqb + 16*O;           // 8 warps * 8

    const int tid = threadIdx.x;

    for (int i = tid; i < O*2*C; i += 256) sW[i] = W[i];
    for (int i = tid; i < C*16;  i += 256)
        sqf[i] = qf[((size_t)b*C + (i >> 4))*Q + qbase + (i & 15)];
    __syncthreads();

    for (int e = tid; e < 16*O; e += 256) {
        int ql = e / O, o = e - ql*O;
        float acc = 0.f;
        #pragma unroll
        for (int c = 0; c < C; c++) acc = fmaf(sW[o*2*C + C + c], sqf[c*16 + ql], acc);
        sqb[e] = acc;
    }
    __syncthreads();

    const int ql = tid >> 4, k = tid & 15;
    const int q = qbase + ql;
    const int j = idx[((size_t)b*Q + q)*16 + k];

    float e_[C];
    #pragma unroll
    for (int c = 0; c < C; c++)
        e_[c] = kf[((size_t)b*C + c)*NK + j] - sqf[c*16 + ql];

    float* hp = h + ((size_t)b*O*Q + q)*16 + k;
    const float* sqbp = sqb + ql*O;
    const int lane = tid & 31, warp = tid >> 5;

    #pragma unroll
    for (int g = 0; g < 4; g++) {
        float s = 0.f, ss = 0.f;
        for (int o = g*(O/4); o < (g+1)*(O/4); o++) {
            float acc = sqbp[o];
            const float* wr = sW + o*2*C;
            #pragma unroll
            for (int c = 0; c < C; c++) acc = fmaf(wr[c], e_[c], acc);
            hp[(size_t)o*Q*16] = acc;
            s += acc; ss = fmaf(acc, acc, ss);
        }
        #pragma unroll
        for (int off = 16; off; off >>= 1) {
            s  += __shfl_xor_sync(0xFFFFFFFFu, s,  off);
            ss += __shfl_xor_sync(0xFFFFFFFFu, ss, off);
        }
        if (lane == 0) { sred[warp*8 + g*2] = s; sred[warp*8 + g*2 + 1] = ss; }
    }
    __syncthreads();
    if (tid < 8) {
        float t = 0.f;
        #pragma unroll
        for (int w = 0; w < 8; w++) t += sred[w*8 + tid];
        atomicAdd(&stats[b*8 + tid], t);
    }
}

// ---------------- mega kernel 1: knn1 (128 blocks) || fps1 (8 blocks) ----------
__global__ void __launch_bounds__(256) mega1_kernel(const float* __restrict__ pc,
                                                    int* __restrict__ idx1,
                                                    int* __restrict__ fps1)
{
    extern __shared__ char smem[];
    int blk = blockIdx.x;
    if (blk < 128) {
        int b = blk >> 4, chunk = blk & 15;
        knn_dev(pc + (size_t)b*3*NPTS, pc + (size_t)b*3*NPTS, NPTS, NPTS,
                idx1 + (size_t)b*NPTS*16, chunk*256, smem);
    } else {
        int b = blk - 128;
        fps_dev<4096,1024>(pc + (size_t)b*3*NPTS, fps1 + (size_t)b*1024, smem);
    }
}

// ---------------- fused kernel 2: knn3 (32) || fps2 (8) || edge1_h (2048) ------
// Long blocks first so they start in wave 1. knn2 is ELIMINATED: its query
// coords are exact copies of knn1's points over the same key set, so
// idx2 = idx1[fps1] (computed by idx2_gather_kernel).
__global__ void __launch_bounds__(256) fused2_kernel(const float* __restrict__ qc1,
                                                     const float* __restrict__ feat,
                                                     const int* __restrict__ idx1,
                                                     const float* __restrict__ W1,
                                                     float* __restrict__ h,
                                                     float* __restrict__ stats,
                                                     int* __restrict__ idx3,
                                                     int* __restrict__ fps2)
{
    extern __shared__ char smem[];
    int blk = blockIdx.x;
    if (blk < 32) {
        int b = blk >> 2, chunk = blk & 3;
        knn_dev(qc1 + (size_t)b*3*1024, qc1 + (size_t)b*3*1024, 1024, 1024,
                idx3 + (size_t)b*1024*16, chunk*256, smem);
    } else if (blk < 40) {
        int b = blk - 32;
        fps_dev<1024,256>(qc1 + (size_t)b*3*1024, fps2 + (size_t)b*256, smem);
    } else {
        int e = blk - 40;                 // 0..2047
        int b = e >> 8, qt = e & 255;
        edge_h_dev<8,32>(feat, feat, idx1, W1, h, stats, NPTS, NPTS, b, qt*16, smem);
    }
}

// ---------------- idx2 = idx1[fps1] (knn2 elimination) -------------------------
__global__ void idx2_gather_kernel(const int* __restrict__ idx1, const int* __restrict__ fps1,
                                   int* __restrict__ idx2)
{
    int i = blockIdx.x*256 + threadIdx.x;          // over B*1024*16
    if (i >= BATCH*1024*16) return;
    int s = i & 15; int m = (i >> 4) & 1023; int b = i >> 14;
    idx2[i] = idx1[((size_t)b*NPTS + fps1[b*1024 + m])*16 + s];
}

// ---------------- knn4 (needs gathered out coords) ----------------
__global__ void __launch_bounds__(256) knn4_kernel(const float* __restrict__ qc,
                                                   int* __restrict__ idx4)
{
    extern __shared__ char smem[];
    int b = blockIdx.x;
    knn_dev(qc + (size_t)b*3*256, qc + (size_t)b*3*256, 256, 256,
            idx4 + (size_t)b*256*16, 0, smem);
}

// ---------------- gather: dst[b,c,m] = src[b,c,idx[b,m]] ----------------
__global__ void gather_kernel(const float* __restrict__ src, const int* __restrict__ idx,
                              float* __restrict__ dst, int C, int Nsrc, int M)
{
    int i = blockIdx.x*256 + threadIdx.x;
    if (i >= BATCH*C*M) return;
    int m = i % M; int c = (i/M) % C; int b = i/(M*C);
    dst[i] = src[((size_t)b*C + c)*Nsrc + idx[(size_t)b*M + m]];
}

// ---------------- edge conv wrappers (stages 2,3,4) ----------------
template<int C, int O>
__global__ void edge_h_kernel(const float* __restrict__ kf, const float* __restrict__ qf,
                              const int* __restrict__ idx, const float* __restrict__ W,
                              float* __restrict__ h, float* __restrict__ stats,
                              int Q, int NK)
{
    extern __shared__ char smemc[];
    edge_h_dev<C,O>(kf, qf, idx, W, h, stats, Q, NK, blockIdx.y, blockIdx.x*16, smemc);
}

// ---------------- stats ----------------
__global__ void zero_stats_kernel(float* __restrict__ stats)
{
    int i = threadIdx.x;
    if (i < 64) stats[i] = 0.f;
}
__global__ void stats_fin_kernel(const float* __restrict__ stats, float* __restrict__ musig,
                                 float inv_cnt)
{
    int i = threadIdx.x;
    if (i < 32) {
        float s = stats[i*2], ss = stats[i*2+1];
        float mu  = s * inv_cnt;
        float var = ss * inv_cnt - mu*mu;
        musig[i*2]   = mu;
        musig[i*2+1] = 1.0f / sqrtf(var + 1e-5f);
    }
}

// ---------------- edge conv pass 2: GN + leaky + max over k ----------------
__global__ void edge_out_kernel(const float* __restrict__ h, const float* __restrict__ musig,
                                const float* __restrict__ gamma, const float* __restrict__ beta,
                                float* __restrict__ out, int O, int O4, int Q)
{
    int i = blockIdx.x*256 + threadIdx.x;
    if (i >= BATCH*O*Q) return;
    int o = (i / Q) % O;
    int b = i / (Q*O);
    int g = o / O4;
    float mu   = musig[(b*4+g)*2];
    float rstd = musig[(b*4+g)*2+1];
    float ga = gamma[o], be = beta[o];
    const float4* hp = (const float4*)(h + (size_t)i*16);
    float m = -INFINITY;
    #pragma unroll
    for (int r = 0; r < 4; r++) {
        float4 v = hp[r];
        float vv[4] = {v.x, v.y, v.z, v.w};
        #pragma unroll
        for (int c = 0; c < 4; c++) {
            float xn = (vv[c] - mu) * rstd;
            float y  = xn * ga + be;
            y = (y >= 0.f) ? y : 0.2f * y;
            m = fmaxf(m, y);
        }
    }
    out[i] = m;
}

// ---------------- host orchestration ----------------
static inline int eh_smem(int C, int O) { return (O*2*C + 16*C + 16*O + 64) * 4; }
#define KNN_SMEM 49152

extern "C" void kernel_launch(void* const* d_in, const int* in_sizes, int n_in,
                              void* d_out, int out_size)
{
    const float* pc = (const float*)d_in[0];
    const float* Wt = (const float*)d_in[1];
    const float* bt = (const float*)d_in[2];
    const float* W1 = (const float*)d_in[3];
    const float* g1 = (const float*)d_in[4];
    const float* b1 = (const float*)d_in[5];
    const float* W2 = (const float*)d_in[6];
    const float* g2 = (const float*)d_in[7];
    const float* b2 = (const float*)d_in[8];
    const float* W3 = (const float*)d_in[9];
    const float* g3 = (const float*)d_in[10];
    const float* b3 = (const float*)d_in[11];
    const float* W4 = (const float*)d_in[12];
    const float* g4 = (const float*)d_in[13];
    const float* b4 = (const float*)d_in[14];
    float* out = (float*)d_out;

    float *feat, *h, *kf1, *qc1, *qf1, *qf2, *kf3, *qf4, *stats, *musig;
    int *idx1, *idx2, *idx3, *idx4, *fps1, *fps2;
    cudaGetSymbolAddress((void**)&feat,  g_feat);
    cudaGetSymbolAddress((void**)&h,     g_h);
    cudaGetSymbolAddress((void**)&kf1,   g_kf1);
    cudaGetSymbolAddress((void**)&qc1,   g_qc1);
    cudaGetSymbolAddress((void**)&qf1,   g_qf1);
    cudaGetSymbolAddress((void**)&qf2,   g_qf2);
    cudaGetSymbolAddress((void**)&kf3,   g_kf3);
    cudaGetSymbolAddress((void**)&qf4,   g_qf4);
    cudaGetSymbolAddress((void**)&stats, g_stats);
    cudaGetSymbolAddress((void**)&musig, g_musig);
    cudaGetSymbolAddress((void**)&idx1,  g_idx1);
    cudaGetSymbolAddress((void**)&idx2,  g_idx2);
    cudaGetSymbolAddress((void**)&idx3,  g_idx3);
    cudaGetSymbolAddress((void**)&idx4,  g_idx4);
    cudaGetSymbolAddress((void**)&fps1,  g_fps1);
    cudaGetSymbolAddress((void**)&fps2,  g_fps2);

    cudaFuncSetAttribute(edge_h_kernel<64,128>,
                         cudaFuncAttributeMaxDynamicSharedMemorySize, eh_smem(64,128));

    // stage 0
    transform_kernel<<<(BATCH*8*NPTS+255)/256, 256>>>(pc, Wt, bt, feat);
    zero_stats_kernel<<<1,64>>>(stats);

    // mega1: knn1 (128) || fps1 (8), one wave of 136
    mega1_kernel<<<136, 256, KNN_SMEM>>>(pc, idx1, fps1);

    // qc1 gather (only fps1-dependent; unblocks fused2)
    gather_kernel<<<(BATCH*3*1024+255)/256, 256>>>(pc, fps1, qc1, 3, NPTS, 1024);

    // fused2: knn3 (32) || fps2 (8) || edge1_h (2048)
    fused2_kernel<<<2088, 256, KNN_SMEM>>>(qc1, feat, idx1, W1, h, stats, idx3, fps2);

    // idx2 = idx1[fps1]  (knn2 eliminated)
    idx2_gather_kernel<<<(BATCH*1024*16+255)/256, 256>>>(idx1, fps1, idx2);

    // edge_conv 1 epilogue
    stats_fin_kernel<<<1,32>>>(stats, musig, 1.0f/524288.0f);
    edge_out_kernel<<<(BATCH*32*NPTS+255)/256, 256>>>(h, musig, g1, b1, kf1, 32, 8, NPTS);
    gather_kernel<<<(BATCH*32*1024+255)/256,256>>>(kf1, fps1, qf1, 32, NPTS, 1024);

    // edge_conv 2: C=32 -> O=64 (idx2, keys = full 4096 set)
    zero_stats_kernel<<<1,64>>>(stats);
    edge_h_kernel<32,64><<<dim3(1024/16, BATCH), 256, eh_smem(32,64)>>>(kf1, qf1, idx2, W2, h, stats, 1024, NPTS);
    stats_fin_kernel<<<1,32>>>(stats, musig, 1.0f/262144.0f);
    edge_out_kernel<<<(BATCH*64*1024+255)/256, 256>>>(h, musig, g2, b2, qf2, 64, 16, 1024);

    // edge_conv 3: C=64 -> O=64 (idx3 from fused2)
    zero_stats_kernel<<<1,64>>>(stats);
    edge_h_kernel<64,64><<<dim3(1024/16, BATCH), 256, eh_smem(64,64)>>>(qf2, qf2, idx3, W3, h, stats, 1024, 1024);
    stats_fin_kernel<<<1,32>>>(stats, musig, 1.0f/262144.0f);
    edge_out_kernel<<<(BATCH*64*1024+255)/256, 256>>>(h, musig, g3, b3, kf3, 64, 16, 1024);

    // fps2 gathers (coords straight into d_out) + knn4
    gather_kernel<<<(BATCH*3*256+255)/256, 256>>>(qc1, fps2, out, 3, 1024, 256);
    gather_kernel<<<(BATCH*64*256+255)/256,256>>>(kf3, fps2, qf4, 64, 1024, 256);
    knn4_kernel<<<8, 256, KNN_SMEM>>>(out, idx4);

    // edge_conv 4: C=64 -> O=128
    zero_stats_kernel<<<1,64>>>(stats);
    edge_h_kernel<64,128><<<dim3(256/16, BATCH), 256, eh_smem(64,128)>>>(qf4, qf4, idx4, W4, h, stats, 256, 256);
    stats_fin_kernel<<<1,32>>>(stats, musig, 1.0f/131072.0f);
    edge_out_kernel<<<(BATCH*128*256+255)/256, 256>>>(h, musig, g4, b4, out + BATCH*3*256, 128, 32, 256);
}